// round 5
// baseline (speedup 1.0000x reference)
#include <cuda_runtime.h>
#include <math.h>

#define SEQ  40
#define H    4096
#define OUT  128
#define NBLK 256
#define NTHR 512
#define JPB  (H / NBLK)     // 16 hidden indices per block
#define ROWS (4 * H)        // 16384 gate rows
#define RQ4  (H / 16)       // 256 uint4 (16 int8 weights) per row

typedef unsigned long long u64;

// ---- persistent device state (no allocations allowed) ----
__device__ float    g_h[2][H];                                  // ping-pong hidden state
__device__ float    g_scale[ROWS];                              // per-row dequant scale
__device__ __align__(256) unsigned g_wq[(size_t)ROWS * (H / 4)];// 67 MB biased-u8 weights
__device__ unsigned g_bar_count = 0;
__device__ unsigned g_bar_gen   = 0;

// ---------------- packed f32x2 helpers ----------------
__device__ __forceinline__ u64 pack64(unsigned lo, unsigned hi) {
    u64 r; asm("mov.b64 %0, {%1,%2};" : "=l"(r) : "r"(lo), "r"(hi)); return r;
}
__device__ __forceinline__ u64 packf2(float lo, float hi) {
    u64 r; asm("mov.b64 %0, {%1,%2};" : "=l"(r) : "f"(lo), "f"(hi)); return r;
}
__device__ __forceinline__ void unpackf2(u64 v, float& lo, float& hi) {
    asm("mov.b64 {%0,%1}, %2;" : "=f"(lo), "=f"(hi) : "l"(v));
}
__device__ __forceinline__ u64 addx2(u64 a, u64 b) {
    u64 r; asm("add.rn.f32x2 %0, %1, %2;" : "=l"(r) : "l"(a), "l"(b)); return r;
}
__device__ __forceinline__ u64 fmax2(u64 a, u64 b, u64 c) {
    u64 r; asm("fma.rn.f32x2 %0, %1, %2, %3;" : "=l"(r) : "l"(a), "l"(b), "l"(c)); return r;
}

// -8388736.0f = -(2^23 + 128) in both lanes (removes magic + bias exactly)
#define NEG_MAGIC 0xCB000080u

// ---------------- grid barrier ----------------
__device__ __forceinline__ void grid_barrier() {
    __syncthreads();
    if (threadIdx.x == 0) {
        unsigned gen = atomicAdd(&g_bar_gen, 0u);
        __threadfence();
        if (atomicAdd(&g_bar_count, 1u) == NBLK - 1u) {
            g_bar_count = 0;
            __threadfence();
            atomicAdd(&g_bar_gen, 1u);
        } else {
            volatile unsigned* vg = &g_bar_gen;
            while (*vg == gen) { }
            __threadfence();
        }
    }
    __syncthreads();
}

// ---------------- int8 quantization prologue (unchanged from R4) ----------------
__global__ __launch_bounds__(256) void quant_kernel(const float* __restrict__ w_hh) {
    const int warp = threadIdx.x >> 5, lane = threadIdx.x & 31;
    const int r = blockIdx.x * 8 + warp;
    const float4* row = (const float4*)(w_hh + (size_t)r * H);
    float mx = 0.0f;
    #pragma unroll 8
    for (int c = lane; c < H / 4; c += 32) {
        float4 v = __ldg(row + c);
        mx = fmaxf(mx, fmaxf(fmaxf(fabsf(v.x), fabsf(v.y)),
                             fmaxf(fabsf(v.z), fabsf(v.w))));
    }
    #pragma unroll
    for (int o = 16; o > 0; o >>= 1) mx = fmaxf(mx, __shfl_xor_sync(0xffffffffu, mx, o));
    const float inv = (mx > 0.0f) ? 127.0f / mx : 0.0f;
    if (lane == 0) g_scale[r] = mx * (1.0f / 127.0f);

    uint4* dst = (uint4*)g_wq + (size_t)r * RQ4;
    for (int c = lane; c < RQ4; c += 32) {
        unsigned m[16];
        #pragma unroll
        for (int q = 0; q < 4; ++q) {
            float4 v = __ldg(row + 4 * c + q);
            m[4 * q + 0] = __float_as_uint(fmaf(v.x, inv, 128.0f) + 8388608.0f);
            m[4 * q + 1] = __float_as_uint(fmaf(v.y, inv, 128.0f) + 8388608.0f);
            m[4 * q + 2] = __float_as_uint(fmaf(v.z, inv, 128.0f) + 8388608.0f);
            m[4 * q + 3] = __float_as_uint(fmaf(v.w, inv, 128.0f) + 8388608.0f);
        }
        uint4 o;
        #pragma unroll
        for (int q = 0; q < 4; ++q) {
            unsigned t0 = __byte_perm(m[4 * q + 0], m[4 * q + 1], 0x0040);
            unsigned t1 = __byte_perm(m[4 * q + 2], m[4 * q + 3], 0x0040);
            ((unsigned*)&o)[q] = __byte_perm(t0, t1, 0x5410);
        }
        dst[c] = o;
    }
}

// ---------------- per-warp matvec: 4 consecutive rows (same gate), prefetched ----------------
__device__ __forceinline__ void warp_rows4(const float4 (&hs)[4][257],
                                           int wid, int lane, int j0,
                                           float (&gsm)[4][JPB]) {
    const int rloc0 = wid * 4;                   // rows rloc0..rloc0+3, same gate
    const int gate  = rloc0 >> 4;
    const int jj0   = rloc0 & 15;
    const int grow0 = gate * H + j0 + jj0;       // consecutive rows grow0..grow0+3
    const uint4* base = (const uint4*)g_wq + (size_t)grow0 * RQ4;

    u64 acc[4];
    #pragma unroll
    for (int rr = 0; rr < 4; ++rr) acc[rr] = 0ull;
    const u64 C2 = pack64(NEG_MAGIC, NEG_MAGIC);

    uint4 wc[4], wn[4];
    #pragma unroll
    for (int rr = 0; rr < 4; ++rr) wc[rr] = __ldg(base + rr * RQ4 + lane);

    #pragma unroll
    for (int it = 0; it < RQ4 / 32; ++it) {      // 8 iterations
        const int c = it * 32 + lane;
        if (it < RQ4 / 32 - 1) {
            #pragma unroll
            for (int rr = 0; rr < 4; ++rr) wn[rr] = __ldg(base + rr * RQ4 + c + 32);
        }
        const float4 h0 = hs[0][c], h1 = hs[1][c], h2 = hs[2][c], h3 = hs[3][c];
        u64 hp[8];
        hp[0] = packf2(h0.x, h0.y); hp[1] = packf2(h0.z, h0.w);
        hp[2] = packf2(h1.x, h1.y); hp[3] = packf2(h1.z, h1.w);
        hp[4] = packf2(h2.x, h2.y); hp[5] = packf2(h2.z, h2.w);
        hp[6] = packf2(h3.x, h3.y); hp[7] = packf2(h3.z, h3.w);

        #pragma unroll
        for (int rr = 0; rr < 4; ++rr) {
            u64 a = acc[rr];
            #pragma unroll
            for (int q = 0; q < 4; ++q) {
                const unsigned v = ((const unsigned*)&wc[rr])[q];
                const unsigned f0 = __byte_perm(v, 0x4B000000u, 0x7440);
                const unsigned f1 = __byte_perm(v, 0x4B000000u, 0x7441);
                const unsigned f2 = __byte_perm(v, 0x4B000000u, 0x7442);
                const unsigned f3 = __byte_perm(v, 0x4B000000u, 0x7443);
                a = fmax2(addx2(pack64(f0, f1), C2), hp[2 * q + 0], a);
                a = fmax2(addx2(pack64(f2, f3), C2), hp[2 * q + 1], a);
            }
            acc[rr] = a;
        }
        #pragma unroll
        for (int rr = 0; rr < 4; ++rr) wc[rr] = wn[rr];
    }
    #pragma unroll
    for (int rr = 0; rr < 4; ++rr) {
        float lo, hi;
        unpackf2(acc[rr], lo, hi);
        float a = lo + hi;
        #pragma unroll
        for (int o = 16; o > 0; o >>= 1) a += __shfl_down_sync(0xffffffffu, a, o);
        if (lane == 0)
            gsm[gate][jj0 + rr] = a * g_scale[grow0 + rr];
    }
}

// ---------------- persistent LSTM kernel ----------------
__global__ __launch_bounds__(NTHR, 2)
void lstm_persistent_kernel(const float* __restrict__ x,
                            const float* __restrict__ w_ih,
                            const float* __restrict__ b_ih,
                            const float* __restrict__ b_hh,
                            const float* __restrict__ dense_w,
                            const float* __restrict__ dense_b,
                            float* __restrict__ out) {
    __shared__ float4 h_s[4][257];     // de-interleaved h_{t-1}, padded (conflict-free)
    __shared__ float  gsm[4][JPB];
    __shared__ float  c_s[JPB];
    __shared__ float  red[NTHR / 32];

    const int tid  = threadIdx.x;
    const int lane = tid & 31;
    const int wid  = tid >> 5;
    const int j0   = blockIdx.x * JPB;

    if (tid < JPB) c_s[tid] = 0.0f;

    for (int t = 0; t < SEQ; ++t) {
        if (t > 0) {
            const float4* hb = (const float4*)g_h[(t - 1) & 1];
            #pragma unroll
            for (int k = 0; k < (H / 4) / NTHR; ++k) {
                const int idx = tid + k * NTHR;        // 0..1023
                h_s[idx & 3][idx >> 2] = hb[idx];
            }
            __syncthreads();
            warp_rows4(h_s, wid, lane, j0, gsm);
        }
        __syncthreads();

        if (tid < JPB) {
            const int   j  = j0 + tid;
            const float xt = x[t];
            float v[4];
            #pragma unroll
            for (int g = 0; g < 4; ++g) {
                const int row = g * H + j;
                const float dot = (t > 0) ? gsm[g][tid] : 0.0f;
                v[g] = fmaf(w_ih[row], xt, b_ih[row] + b_hh[row]) + dot;
            }
            const float ig = 1.0f / (1.0f + expf(-v[0]));
            const float fg = 1.0f / (1.0f + expf(-v[1]));
            const float gg = tanhf(v[2]);
            const float og = 1.0f / (1.0f + expf(-v[3]));
            const float c  = fg * c_s[tid] + ig * gg;
            c_s[tid] = c;
            g_h[t & 1][j] = og * tanhf(c);
            __threadfence();
        }
        grid_barrier();
    }

    // Dense epilogue: blocks 0..127 each compute one output row (fp32).
    if (blockIdx.x < OUT) {
        const float* hw = g_h[(SEQ - 1) & 1];
        const float* wr = dense_w + (size_t)blockIdx.x * H;
        float acc = 0.0f;
        #pragma unroll
        for (int k = tid; k < H; k += NTHR)
            acc += wr[k] * hw[k];
        #pragma unroll
        for (int o = 16; o > 0; o >>= 1)
            acc += __shfl_down_sync(0xffffffffu, acc, o);
        if (lane == 0) red[wid] = acc;
        __syncthreads();
        if (tid == 0) {
            float s = 0.0f;
            #pragma unroll
            for (int w = 0; w < NTHR / 32; ++w) s += red[w];
            out[blockIdx.x] = s + dense_b[blockIdx.x];
        }
    }
}

extern "C" void kernel_launch(void* const* d_in, const int* in_sizes, int n_in,
                              void* d_out, int out_size) {
    const float* x       = (const float*)d_in[0];
    const float* w_ih    = (const float*)d_in[1];
    const float* w_hh    = (const float*)d_in[2];
    const float* b_ih    = (const float*)d_in[3];
    const float* b_hh    = (const float*)d_in[4];
    const float* dense_w = (const float*)d_in[5];
    const float* dense_b = (const float*)d_in[6];

    quant_kernel<<<ROWS / 8, 256>>>(w_hh);
    lstm_persistent_kernel<<<NBLK, NTHR>>>(x, w_ih, b_ih, b_hh,
                                           dense_w, dense_b, (float*)d_out);
}